// round 15
// baseline (speedup 1.0000x reference)
#include <cuda_runtime.h>
#include <cuda_bf16.h>
#include <cuda_fp16.h>
#include <math.h>
#include <stdint.h>

#define NN   50000
#define EE   800000
#define ET   (EE + NN)      // 850000 edges incl. self loops
#define FDIM 128
#define NH   4
#define CH   32
#define NEG_SLOPE 0.2f

// ---------------- device scratch (module-load allocated, no cudaMalloc) ----
__device__ int   g_cnt[NN];
__device__ int   g_rowptr[NN + 1];
__device__ int   g_cursor[NN];
__device__ int   g_csr[ET];
__device__ int   g_bsums[256];

__device__ __align__(16) __half g_h2[NN * FDIM];   // features, fp16 (gather)
__device__ __align__(16) __half g_f1h[NN * FDIM];  // layer1 out, fp16 (GEMM2 A)
__device__ float g_alpha[NN * 2 * NH];// per-node alpha_src[0..3], alpha_dst[4..7]
__device__ float g_hw3[NN * 2];
__device__ float g_a3[NN * 2];

// pre-swizzled bf16 hi/lo planes of W, per-half layout:
// [half(0/1)][16KB: rows n=0..127 x 8 chunks of 16B, xor-swizzled]
__device__ __align__(16) uint8_t g_wh[32768];
__device__ __align__(16) uint8_t g_wl[32768];

// ---------------- warp helpers ----------------------------------------------
__device__ __forceinline__ float wsum(float v) {
    #pragma unroll
    for (int o = 16; o; o >>= 1) v += __shfl_xor_sync(0xffffffffu, v, o);
    return v;
}

// ---------------- mma helpers ------------------------------------------------
__device__ __forceinline__ uint32_t smem_u32(const void* p) {
    uint32_t a;
    asm("{ .reg .u64 tmp; cvta.to.shared.u64 tmp, %1; cvt.u32.u64 %0, tmp; }"
        : "=r"(a) : "l"(p));
    return a;
}
__device__ __forceinline__ void ldsm_x4(uint32_t& r0, uint32_t& r1,
                                        uint32_t& r2, uint32_t& r3, uint32_t addr) {
    asm volatile("ldmatrix.sync.aligned.m8n8.x4.shared.b16 {%0,%1,%2,%3}, [%4];"
                 : "=r"(r0), "=r"(r1), "=r"(r2), "=r"(r3) : "r"(addr));
}
__device__ __forceinline__ void mma16816(float* c, uint32_t a0, uint32_t a1,
                                         uint32_t a2, uint32_t a3,
                                         uint32_t b0, uint32_t b1) {
    asm volatile("mma.sync.aligned.m16n8k16.row.col.f32.bf16.bf16.f32 "
                 "{%0,%1,%2,%3}, {%4,%5,%6,%7}, {%8,%9}, {%0,%1,%2,%3};"
                 : "+f"(c[0]), "+f"(c[1]), "+f"(c[2]), "+f"(c[3])
                 : "r"(a0), "r"(a1), "r"(a2), "r"(a3), "r"(b0), "r"(b1));
}
// half-K plane: 128 rows x 64 bf16 (128B rows, 8 chunks of 16B), xor swizzle
__device__ __forceinline__ uint32_t soff64(int r, int kc) {
    return (uint32_t)((r << 7) + (((kc ^ r) & 7) << 4));
}
__device__ __forceinline__ uint32_t pkbf(float x, float y) {
    __nv_bfloat162 p;
    p.x = __float2bfloat16_rn(x);
    p.y = __float2bfloat16_rn(y);
    return *(uint32_t*)&p;
}

// ---------------- CSR construction ------------------------------------------
__global__ void k_zero_cnt() {
    int i = blockIdx.x * blockDim.x + threadIdx.x;
    if (i < NN) g_cnt[i] = 0;
}
__global__ void k_hist(const int* __restrict__ ei) {
    int e = blockIdx.x * blockDim.x + threadIdx.x;
    if (e >= ET) return;
    int dst = (e < EE) ? ei[EE + e] : (e - EE);
    atomicAdd(&g_cnt[dst], 1);
}
__global__ void k_scan_block() {
    __shared__ int sm[256];
    int i = blockIdx.x * 256 + threadIdx.x;
    int v = (i < NN) ? g_cnt[i] : 0;
    sm[threadIdx.x] = v;
    __syncthreads();
    #pragma unroll
    for (int o = 1; o < 256; o <<= 1) {
        int t = (threadIdx.x >= o) ? sm[threadIdx.x - o] : 0;
        __syncthreads();
        sm[threadIdx.x] += t;
        __syncthreads();
    }
    if (i < NN) g_rowptr[i] = sm[threadIdx.x] - v;
    if (threadIdx.x == 255) g_bsums[blockIdx.x] = sm[255];
}
__global__ void k_scan_tops(int nb) {
    __shared__ int sm[256];
    int v = (threadIdx.x < nb) ? g_bsums[threadIdx.x] : 0;
    sm[threadIdx.x] = v;
    __syncthreads();
    #pragma unroll
    for (int o = 1; o < 256; o <<= 1) {
        int t = (threadIdx.x >= o) ? sm[threadIdx.x - o] : 0;
        __syncthreads();
        sm[threadIdx.x] += t;
        __syncthreads();
    }
    g_bsums[threadIdx.x] = sm[threadIdx.x] - v;
}
__global__ void k_scan_finish() {
    int i = blockIdx.x * blockDim.x + threadIdx.x;
    if (i < NN) {
        int r = g_rowptr[i] + g_bsums[i >> 8];
        g_rowptr[i] = r;
        g_cursor[i] = r;
    }
    if (i == 0) g_rowptr[NN] = ET;
}
__global__ void k_scatter(const int* __restrict__ ei) {
    int e = blockIdx.x * blockDim.x + threadIdx.x;
    if (e >= ET) return;
    int src, dst;
    if (e < EE) { src = ei[e]; dst = ei[EE + e]; }
    else        { src = dst = e - EE; }
    int p = atomicAdd(&g_cursor[dst], 1);
    g_csr[p] = src;
}

// ---------------- W prep: fp32 [128k,128n] -> 2 half-K swizzled planes ------
__global__ void k_wprep(const float* __restrict__ W) {
    int i = blockIdx.x * blockDim.x + threadIdx.x;   // 2048 chunks
    if (i >= 2048) return;
    int n = i >> 4, kc = i & 15;
    uint32_t hp[4], lp[4];
    #pragma unroll
    for (int j = 0; j < 4; j++) {
        float w0 = W[(kc * 8 + 2 * j) * 128 + n];
        float w1 = W[(kc * 8 + 2 * j + 1) * 128 + n];
        __nv_bfloat16 h0 = __float2bfloat16_rn(w0);
        __nv_bfloat16 h1 = __float2bfloat16_rn(w1);
        __nv_bfloat162 hh; hh.x = h0; hh.y = h1;
        hp[j] = *(uint32_t*)&hh;
        lp[j] = pkbf(w0 - __bfloat162float(h0), w1 - __bfloat162float(h1));
    }
    int half = kc >> 3;
    uint32_t off = half * 16384 + soff64(n, kc & 7);
    *(uint4*)(g_wh + off) = make_uint4(hp[0], hp[1], hp[2], hp[3]);
    *(uint4*)(g_wl + off) = make_uint4(lp[0], lp[1], lp[2], lp[3]);
}

// ---------------- tensor-core GEMM + fused per-node alpha -------------------
// 128x128 tile, 512 threads (4x4 warps, warp tile 32x32), K in two 64-halves,
// 4 x 16KB smem planes -> 2 CTAs/SM.
// TERMS=3: D = Ah*Wh + Al*Wh + Ah*Wl (fp32 A split).
// TERMS=2: D = A*Wh + A*Wl (A pre-rounded to bf16; used for fp16 input).
template <int TERMS>
__global__ void __launch_bounds__(512, 2)
k_gemm_mma(const float* __restrict__ Af, const __half* __restrict__ Ahalf,
           const float* __restrict__ asrc, const float* __restrict__ adst,
           __half* __restrict__ H2, int M) {
    extern __shared__ __align__(16) char smem[];
    const int S_AH = 0, S_AL = 16384, S_BH = 32768, S_BL = 49152, S_ATT = 65536;
    int t = threadIdx.x;
    int row0 = blockIdx.x * 128;
    uint32_t sb = smem_u32(smem);
    float* att_s = (float*)(smem + S_ATT);      // [0..127] asrc, [128..255] adst

    if (t < 128)              att_s[t] = asrc[t];
    else if (t < 256)         att_s[t] = adst[t - 128];

    int wid = t >> 5, lane = t & 31;
    int wm = wid & 3;          // 4 row groups x 32 rows
    int wn = wid >> 2;         // 4 col groups x 32 cols (= head wn)

    float acc[2][4][4];
    #pragma unroll
    for (int mt = 0; mt < 2; mt++)
        #pragma unroll
        for (int nt = 0; nt < 4; nt++)
            #pragma unroll
            for (int q = 0; q < 4; q++) acc[mt][nt][q] = 0.f;

    int aRow = wm * 32 + (lane & 15);
    int aSel = lane >> 4;
    int bRow = wn * 32 + (lane & 7) + ((lane >> 4) << 3);
    int bSel = (lane >> 3) & 1;

    #pragma unroll
    for (int ks = 0; ks < 2; ks++) {
        if (ks) __syncthreads();     // previous mainloop must finish reading
        // copy pre-swizzled W half planes (2 x 16KB = 2 x 1024 uint4)
        {
            const uint4* wh4 = (const uint4*)g_wh + ks * 1024;
            const uint4* wl4 = (const uint4*)g_wl + ks * 1024;
            uint4* bh = (uint4*)(smem + S_BH);
            uint4* bl = (uint4*)(smem + S_BL);
            #pragma unroll
            for (int i = 0; i < 2; i++) {
                bh[i * 512 + t] = wh4[i * 512 + t];
                bl[i * 512 + t] = wl4[i * 512 + t];
            }
        }
        // convert A rows (128 rows x 8 chunks = 1024 chunks)
        #pragma unroll
        for (int ii = 0; ii < 2; ii++) {
            int i = ii * 512 + t;
            int r = i >> 3, kc = i & 7;
            int gr = row0 + r;
            int col = ks * 64 + kc * 8;
            float4 v0 = make_float4(0.f, 0.f, 0.f, 0.f), v1 = v0;
            if (gr < M) {
                if (TERMS == 2) {
                    uint4 raw = *(const uint4*)&Ahalf[gr * 128 + col];
                    float2 f0 = __half22float2(*(__half2*)&raw.x);
                    float2 f1p = __half22float2(*(__half2*)&raw.y);
                    float2 f2 = __half22float2(*(__half2*)&raw.z);
                    float2 f3 = __half22float2(*(__half2*)&raw.w);
                    v0 = make_float4(f0.x, f0.y, f1p.x, f1p.y);
                    v1 = make_float4(f2.x, f2.y, f3.x, f3.y);
                } else {
                    v0 = *(const float4*)&Af[gr * 128 + col];
                    v1 = *(const float4*)&Af[gr * 128 + col + 4];
                }
            }
            __nv_bfloat162 h0, h1, h2, h3;
            h0.x = __float2bfloat16_rn(v0.x); h0.y = __float2bfloat16_rn(v0.y);
            h1.x = __float2bfloat16_rn(v0.z); h1.y = __float2bfloat16_rn(v0.w);
            h2.x = __float2bfloat16_rn(v1.x); h2.y = __float2bfloat16_rn(v1.y);
            h3.x = __float2bfloat16_rn(v1.z); h3.y = __float2bfloat16_rn(v1.w);
            uint32_t off = soff64(r, kc);
            *(uint4*)(smem + S_AH + off) = make_uint4(*(uint32_t*)&h0, *(uint32_t*)&h1,
                                                      *(uint32_t*)&h2, *(uint32_t*)&h3);
            if (TERMS == 3) {
                *(uint4*)(smem + S_AL + off) = make_uint4(
                    pkbf(v0.x - __bfloat162float(h0.x), v0.y - __bfloat162float(h0.y)),
                    pkbf(v0.z - __bfloat162float(h1.x), v0.w - __bfloat162float(h1.y)),
                    pkbf(v1.x - __bfloat162float(h2.x), v1.y - __bfloat162float(h2.y)),
                    pkbf(v1.z - __bfloat162float(h3.x), v1.w - __bfloat162float(h3.y)));
            }
        }
        __syncthreads();

        // mainloop over this K half (4 x k16)
        #pragma unroll
        for (int k16 = 0; k16 < 4; k16++) {
            int kc = k16 * 2;
            uint32_t ah[2][4], al[2][4];
            #pragma unroll
            for (int mt = 0; mt < 2; mt++) {
                ldsm_x4(ah[mt][0], ah[mt][1], ah[mt][2], ah[mt][3],
                        sb + S_AH + soff64(aRow + mt * 16, kc + aSel));
                if (TERMS == 3)
                    ldsm_x4(al[mt][0], al[mt][1], al[mt][2], al[mt][3],
                            sb + S_AL + soff64(aRow + mt * 16, kc + aSel));
            }
            #pragma unroll
            for (int np = 0; np < 2; np++) {
                uint32_t bh0, bh1, bh2, bh3, bl0, bl1, bl2, bl3;
                ldsm_x4(bh0, bh1, bh2, bh3, sb + S_BH + soff64(bRow + np * 16, kc + bSel));
                ldsm_x4(bl0, bl1, bl2, bl3, sb + S_BL + soff64(bRow + np * 16, kc + bSel));
                #pragma unroll
                for (int mt = 0; mt < 2; mt++) {
                    mma16816(acc[mt][np * 2],     ah[mt][0], ah[mt][1], ah[mt][2], ah[mt][3], bh0, bh1);
                    mma16816(acc[mt][np * 2 + 1], ah[mt][0], ah[mt][1], ah[mt][2], ah[mt][3], bh2, bh3);
                    if (TERMS == 3) {
                        mma16816(acc[mt][np * 2],     al[mt][0], al[mt][1], al[mt][2], al[mt][3], bh0, bh1);
                        mma16816(acc[mt][np * 2 + 1], al[mt][0], al[mt][1], al[mt][2], al[mt][3], bh2, bh3);
                    }
                    mma16816(acc[mt][np * 2],     ah[mt][0], ah[mt][1], ah[mt][2], ah[mt][3], bl0, bl1);
                    mma16816(acc[mt][np * 2 + 1], ah[mt][0], ah[mt][1], ah[mt][2], ah[mt][3], bl2, bl3);
                }
            }
        }
    }

    // epilogue: fp16 feature store + fused alpha (head h = wn)
    #pragma unroll
    for (int mt = 0; mt < 2; mt++) {
        int rg = row0 + wm * 32 + mt * 16 + (lane >> 2);
        #pragma unroll
        for (int nt = 0; nt < 4; nt++) {
            int n = wn * 32 + nt * 8 + (lane & 3) * 2;
            if (rg < M) {
                __half2 hv; hv.x = __float2half(acc[mt][nt][0]); hv.y = __float2half(acc[mt][nt][1]);
                *(__half2*)&H2[rg * 128 + n] = hv;
            }
            if (rg + 8 < M) {
                __half2 hv; hv.x = __float2half(acc[mt][nt][2]); hv.y = __float2half(acc[mt][nt][3]);
                *(__half2*)&H2[(rg + 8) * 128 + n] = hv;
            }
        }
        float ps0 = 0.f, pd0 = 0.f, ps1 = 0.f, pd1 = 0.f;
        #pragma unroll
        for (int nt = 0; nt < 4; nt++) {
            int n = wn * 32 + nt * 8 + (lane & 3) * 2;
            float w0s = att_s[n], w1s = att_s[n + 1];
            float w0d = att_s[128 + n], w1d = att_s[128 + n + 1];
            ps0 += acc[mt][nt][0] * w0s + acc[mt][nt][1] * w1s;
            pd0 += acc[mt][nt][0] * w0d + acc[mt][nt][1] * w1d;
            ps1 += acc[mt][nt][2] * w0s + acc[mt][nt][3] * w1s;
            pd1 += acc[mt][nt][2] * w0d + acc[mt][nt][3] * w1d;
        }
        #pragma unroll
        for (int o = 1; o <= 2; o <<= 1) {
            ps0 += __shfl_xor_sync(0xffffffffu, ps0, o);
            pd0 += __shfl_xor_sync(0xffffffffu, pd0, o);
            ps1 += __shfl_xor_sync(0xffffffffu, ps1, o);
            pd1 += __shfl_xor_sync(0xffffffffu, pd1, o);
        }
        if ((lane & 3) == 0) {
            if (rg < M) {
                g_alpha[rg * 8 + wn]     = ps0;
                g_alpha[rg * 8 + 4 + wn] = pd0;
            }
            if (rg + 8 < M) {
                g_alpha[(rg + 8) * 8 + wn]     = ps1;
                g_alpha[(rg + 8) * 8 + 4 + wn] = pd1;
            }
        }
    }
}

// ---------------- edge softmax + aggregation (H=4, C=32) --------------------
// TWO warps per node: warp sub=0/1 processes interleaved 32-edge chunks
// (sums and accumulators are purely additive since there is no max-shift);
// partials combined through smem with one uniform __syncthreads.
// Gather layout identical to R13: lane = channel pair, serial edges via smem.
// mode 0: write ELU(out) fp16 to `outh`; mode 1: fused layer-3 prep.
__global__ void k_aggregate4(const __half* __restrict__ h2,
                             const float* __restrict__ bias,
                             __half* __restrict__ outh, int mode,
                             const float* __restrict__ W3,
                             const float* __restrict__ as3,
                             const float* __restrict__ ad3) {
    __shared__ float4 sm_e[8][32];
    __shared__ int    sm_s[8][32];
    __shared__ float  sm_c[4][32][9];    // sub1 partials (padded, no conflicts)
    int n = (blockIdx.x * blockDim.x + threadIdx.x) >> 6;   // 4 nodes per block
    int lane = threadIdx.x & 31;
    int wrp  = threadIdx.x >> 5;        // 0..7 (staging row)
    int sub  = wrp & 1;                 // which half of the edge list
    int ng   = wrp >> 1;                // node index within block 0..3
    int hsel = lane >> 4;
    int s0 = g_rowptr[n], s1 = g_rowptr[n + 1];
    float4 ad = *(const float4*)&g_alpha[n * 8 + 4];

    float sum0 = 0.f, sum1 = 0.f, sum2 = 0.f, sum3 = 0.f;
    float2 accA = make_float2(0.f, 0.f), accB = make_float2(0.f, 0.f);
    for (int base = s0 + sub * 32; base < s1; base += 64) {
        int i = base + lane;
        int s = 0;
        float4 e = make_float4(0.f, 0.f, 0.f, 0.f);
        if (i < s1) {
            s = g_csr[i];
            float4 al = *(const float4*)&g_alpha[s * 8];
            float a;
            a = al.x + ad.x; a = (a > 0.f) ? a : NEG_SLOPE * a; e.x = __expf(a); sum0 += e.x;
            a = al.y + ad.y; a = (a > 0.f) ? a : NEG_SLOPE * a; e.y = __expf(a); sum1 += e.y;
            a = al.z + ad.z; a = (a > 0.f) ? a : NEG_SLOPE * a; e.z = __expf(a); sum2 += e.z;
            a = al.w + ad.w; a = (a > 0.f) ? a : NEG_SLOPE * a; e.w = __expf(a); sum3 += e.w;
        }
        sm_s[wrp][lane] = s;
        sm_e[wrp][lane] = e;
        __syncwarp();
        int cnt = min(32, s1 - base);
        #pragma unroll 4
        for (int j = 0; j < cnt; j++) {
            int ss = sm_s[wrp][j];
            float4 ee = sm_e[wrp][j];
            const __half2* hp = (const __half2*)(h2 + ss * FDIM);
            float2 fa = __half22float2(hp[lane]);
            float2 fb = __half22float2(hp[32 + lane]);
            float wA = hsel ? ee.y : ee.x;
            float wB = hsel ? ee.w : ee.z;
            accA.x += wA * fa.x; accA.y += wA * fa.y;
            accB.x += wB * fb.x; accB.y += wB * fb.y;
        }
        __syncwarp();
    }

    // combine the two warps' partials (per-lane)
    if (sub == 1) {
        float* c = sm_c[ng][lane];
        c[0] = sum0; c[1] = sum1; c[2] = sum2; c[3] = sum3;
        c[4] = accA.x; c[5] = accA.y; c[6] = accB.x; c[7] = accB.y;
    }
    __syncthreads();
    if (sub == 1) return;
    {
        const float* c = sm_c[ng][lane];
        sum0 += c[0]; sum1 += c[1]; sum2 += c[2]; sum3 += c[3];
        accA.x += c[4]; accA.y += c[5]; accB.x += c[6]; accB.y += c[7];
    }

    float inv0 = 1.f / wsum(sum0);
    float inv1 = 1.f / wsum(sum1);
    float inv2 = 1.f / wsum(sum2);
    float inv3 = 1.f / wsum(sum3);
    float invA = hsel ? inv1 : inv0;
    float invB = hsel ? inv3 : inv2;

    int c = 2 * lane;
    float v0 = accA.x * invA + bias[c];
    float v1 = accA.y * invA + bias[c + 1];
    float v2 = accB.x * invB + bias[64 + c];
    float v3 = accB.y * invB + bias[64 + c + 1];
    v0 = (v0 > 0.f) ? v0 : (__expf(v0) - 1.f);
    v1 = (v1 > 0.f) ? v1 : (__expf(v1) - 1.f);
    v2 = (v2 > 0.f) ? v2 : (__expf(v2) - 1.f);
    v3 = (v3 > 0.f) ? v3 : (__expf(v3) - 1.f);

    if (mode == 0) {
        __half2 o0; o0.x = __float2half(v0); o0.y = __float2half(v1);
        __half2 o1; o1.x = __float2half(v2); o1.y = __float2half(v3);
        *(__half2*)&outh[n * FDIM + c]      = o0;
        *(__half2*)&outh[n * FDIM + 64 + c] = o1;
    } else {
        // layer-3 prep: hw3 = f2 @ W3 ([128,2]); a3 from as3/ad3
        float4 wA4 = *(const float4*)&W3[2 * c];
        float4 wB4 = *(const float4*)&W3[128 + 2 * c];
        float p0 = v0 * wA4.x + v1 * wA4.z + v2 * wB4.x + v3 * wB4.z;
        float p1 = v0 * wA4.y + v1 * wA4.w + v2 * wB4.y + v3 * wB4.w;
        p0 = wsum(p0); p1 = wsum(p1);
        if (lane == 0) {
            g_hw3[n * 2] = p0; g_hw3[n * 2 + 1] = p1;
            g_a3[n * 2]     = p0 * as3[0] + p1 * as3[1];
            g_a3[n * 2 + 1] = p0 * ad3[0] + p1 * ad3[1];
        }
    }
}

// layer-3 aggregate (H=1,C=2) + bias + log_softmax, single edge pass
__global__ void k_aggregate1(const float* __restrict__ b3, float* __restrict__ out) {
    int n = (blockIdx.x * blockDim.x + threadIdx.x) >> 5;
    if (n >= NN) return;
    int lane = threadIdx.x & 31;
    int s0 = g_rowptr[n], s1 = g_rowptr[n + 1];
    float ad = g_a3[n * 2 + 1];

    float sum = 0.f, a0 = 0.f, a1 = 0.f;
    for (int i = s0 + lane; i < s1; i += 32) {
        int s = g_csr[i];
        float2 al = *(const float2*)&g_a3[s * 2];
        float a = al.x + ad;
        a = (a > 0.f) ? a : NEG_SLOPE * a;
        float e = __expf(a);
        sum += e;
        float2 h = *(const float2*)&g_hw3[s * 2];
        a0 += e * h.x;
        a1 += e * h.y;
    }
    sum = wsum(sum); a0 = wsum(a0); a1 = wsum(a1);

    if (lane == 0) {
        float inv = 1.f / sum;
        float z0 = a0 * inv + b3[0];
        float z1 = a1 * inv + b3[1];
        float mx = fmaxf(z0, z1);
        float l  = logf(__expf(z0 - mx) + __expf(z1 - mx));
        out[n * 2]     = z0 - mx - l;
        out[n * 2 + 1] = z1 - mx - l;
    }
}

// ---------------- host driver -----------------------------------------------
extern "C" void kernel_launch(void* const* d_in, const int* in_sizes, int n_in,
                              void* d_out, int out_size) {
    const float* x   = (const float*)d_in[0];
    const int*   ei  = (const int*)  d_in[1];
    const float* W1  = (const float*)d_in[2];
    const float* as1 = (const float*)d_in[3];
    const float* ad1 = (const float*)d_in[4];
    const float* b1  = (const float*)d_in[5];
    const float* W2  = (const float*)d_in[6];
    const float* as2 = (const float*)d_in[7];
    const float* ad2 = (const float*)d_in[8];
    const float* b2  = (const float*)d_in[9];
    const float* W3  = (const float*)d_in[10];
    const float* as3 = (const float*)d_in[11];
    const float* ad3 = (const float*)d_in[12];
    const float* b3  = (const float*)d_in[13];
    float* out = (float*)d_out;

    __half *p_h2, *p_f1h;
    cudaGetSymbolAddress((void**)&p_h2, g_h2);
    cudaGetSymbolAddress((void**)&p_f1h, g_f1h);

    const int GEMM_SMEM = 65536 + 1024;    // 4 x 16KB planes + att
    cudaFuncSetAttribute(k_gemm_mma<3>, cudaFuncAttributeMaxDynamicSharedMemorySize, GEMM_SMEM);
    cudaFuncSetAttribute(k_gemm_mma<2>, cudaFuncAttributeMaxDynamicSharedMemorySize, GEMM_SMEM);

    // one-time host resources
    static cudaStream_t s1 = nullptr;
    static cudaEvent_t evFork = nullptr, evCsr = nullptr, evG1 = nullptr, evW2 = nullptr;
    if (!s1) {
        cudaStreamCreateWithFlags(&s1, cudaStreamNonBlocking);
        cudaEventCreateWithFlags(&evFork, cudaEventDisableTiming);
        cudaEventCreateWithFlags(&evCsr,  cudaEventDisableTiming);
        cudaEventCreateWithFlags(&evG1,   cudaEventDisableTiming);
        cudaEventCreateWithFlags(&evW2,   cudaEventDisableTiming);
    }

    const int TPB = 256;
    int nbN = (NN + TPB - 1) / TPB;           // 196
    int nbE = (ET + TPB - 1) / TPB;           // 3321
    int nbW = (NN * 32 + TPB - 1) / TPB;      // 6250 (warp per node)
    int nbW2 = (NN * 64) / TPB;               // 12500 (2 warps per node, exact)
    int nbT = (NN + 127) / 128;               // 391 gemm tiles

    // fork: CSR branch on s1, GEMM branch on the launch stream (0)
    cudaEventRecord(evFork, 0);
    cudaStreamWaitEvent(s1, evFork, 0);

    // --- branch A (s1): CSR build ---
    k_zero_cnt<<<nbN, TPB, 0, s1>>>();
    k_hist<<<nbE, TPB, 0, s1>>>(ei);
    k_scan_block<<<nbN, TPB, 0, s1>>>();
    k_scan_tops<<<1, 256, 0, s1>>>(nbN);
    k_scan_finish<<<nbN, TPB, 0, s1>>>();
    k_scatter<<<nbE, TPB, 0, s1>>>(ei);
    cudaEventRecord(evCsr, s1);

    // --- branch B (stream 0): W1 prep + GEMM1 ---
    k_wprep<<<16, 128>>>(W1);
    k_gemm_mma<3><<<nbT, 512, GEMM_SMEM>>>(x, nullptr, as1, ad1, p_h2, NN);
    cudaEventRecord(evG1, 0);

    // W2 prep on s1, overlapped with layer-1 aggregation
    cudaStreamWaitEvent(s1, evG1, 0);
    k_wprep<<<16, 128, 0, s1>>>(W2);
    cudaEventRecord(evW2, s1);

    // join: layer-1 aggregation needs CSR + GEMM1
    cudaStreamWaitEvent(0, evCsr, 0);
    k_aggregate4<<<nbW2, TPB>>>(p_h2, b1, p_f1h, 0, W3, as3, ad3);

    // layer 2 (needs W2 planes)
    cudaStreamWaitEvent(0, evW2, 0);
    k_gemm_mma<2><<<nbT, 512, GEMM_SMEM>>>(nullptr, p_f1h, as2, ad2, p_h2, NN);
    k_aggregate4<<<nbW2, TPB>>>(p_h2, b2, nullptr, 1, W3, as3, ad3);

    // layer 3 final aggregate + log_softmax
    k_aggregate1<<<nbW, TPB>>>(b3, out);
}

// round 16
// speedup vs baseline: 1.2511x; 1.2511x over previous
#include <cuda_runtime.h>
#include <cuda_bf16.h>
#include <cuda_fp16.h>
#include <math.h>
#include <stdint.h>

#define NN   50000
#define EE   800000
#define ET   (EE + NN)      // 850000 edges incl. self loops
#define FDIM 128
#define NH   4
#define CH   32
#define NEG_SLOPE 0.2f

// ---------------- device scratch (module-load allocated, no cudaMalloc) ----
__device__ int   g_cnt[NN];
__device__ int   g_rowptr[NN + 1];
__device__ int   g_cursor[NN];
__device__ int   g_csr[ET];
__device__ int   g_bsums[256];

__device__ __align__(16) __half g_h2[NN * FDIM];   // features, fp16 (gather)
__device__ __align__(16) __half g_f1h[NN * FDIM];  // layer1 out, fp16 (GEMM2 A)
__device__ float g_alpha[NN * 2 * NH];// per-node alpha_src[0..3], alpha_dst[4..7]
__device__ float g_hw3[NN * 2];
__device__ float g_a3[NN * 2];

// pre-swizzled bf16 hi/lo planes of W, per-half layout:
// [half(0/1)][16KB: rows n=0..127 x 8 chunks of 16B, xor-swizzled]
__device__ __align__(16) uint8_t g_wh[32768];
__device__ __align__(16) uint8_t g_wl[32768];

// ---------------- warp helpers ----------------------------------------------
__device__ __forceinline__ float wsum(float v) {
    #pragma unroll
    for (int o = 16; o; o >>= 1) v += __shfl_xor_sync(0xffffffffu, v, o);
    return v;
}

// ---------------- mma helpers ------------------------------------------------
__device__ __forceinline__ uint32_t smem_u32(const void* p) {
    uint32_t a;
    asm("{ .reg .u64 tmp; cvta.to.shared.u64 tmp, %1; cvt.u32.u64 %0, tmp; }"
        : "=r"(a) : "l"(p));
    return a;
}
__device__ __forceinline__ void ldsm_x4(uint32_t& r0, uint32_t& r1,
                                        uint32_t& r2, uint32_t& r3, uint32_t addr) {
    asm volatile("ldmatrix.sync.aligned.m8n8.x4.shared.b16 {%0,%1,%2,%3}, [%4];"
                 : "=r"(r0), "=r"(r1), "=r"(r2), "=r"(r3) : "r"(addr));
}
__device__ __forceinline__ void mma16816(float* c, uint32_t a0, uint32_t a1,
                                         uint32_t a2, uint32_t a3,
                                         uint32_t b0, uint32_t b1) {
    asm volatile("mma.sync.aligned.m16n8k16.row.col.f32.bf16.bf16.f32 "
                 "{%0,%1,%2,%3}, {%4,%5,%6,%7}, {%8,%9}, {%0,%1,%2,%3};"
                 : "+f"(c[0]), "+f"(c[1]), "+f"(c[2]), "+f"(c[3])
                 : "r"(a0), "r"(a1), "r"(a2), "r"(a3), "r"(b0), "r"(b1));
}
// half-K plane: 128 rows x 64 bf16 (128B rows, 8 chunks of 16B), xor swizzle
__device__ __forceinline__ uint32_t soff64(int r, int kc) {
    return (uint32_t)((r << 7) + (((kc ^ r) & 7) << 4));
}
__device__ __forceinline__ uint32_t pkbf(float x, float y) {
    __nv_bfloat162 p;
    p.x = __float2bfloat16_rn(x);
    p.y = __float2bfloat16_rn(y);
    return *(uint32_t*)&p;
}

// ---------------- CSR construction ------------------------------------------
__global__ void k_zero_cnt() {
    int i = blockIdx.x * blockDim.x + threadIdx.x;
    if (i < NN) g_cnt[i] = 0;
}
__global__ void k_hist(const int* __restrict__ ei) {
    int e = blockIdx.x * blockDim.x + threadIdx.x;
    if (e >= ET) return;
    int dst = (e < EE) ? ei[EE + e] : (e - EE);
    atomicAdd(&g_cnt[dst], 1);
}
__global__ void k_scan_block() {
    __shared__ int sm[256];
    int i = blockIdx.x * 256 + threadIdx.x;
    int v = (i < NN) ? g_cnt[i] : 0;
    sm[threadIdx.x] = v;
    __syncthreads();
    #pragma unroll
    for (int o = 1; o < 256; o <<= 1) {
        int t = (threadIdx.x >= o) ? sm[threadIdx.x - o] : 0;
        __syncthreads();
        sm[threadIdx.x] += t;
        __syncthreads();
    }
    if (i < NN) g_rowptr[i] = sm[threadIdx.x] - v;
    if (threadIdx.x == 255) g_bsums[blockIdx.x] = sm[255];
}
__global__ void k_scan_tops(int nb) {
    __shared__ int sm[256];
    int v = (threadIdx.x < nb) ? g_bsums[threadIdx.x] : 0;
    sm[threadIdx.x] = v;
    __syncthreads();
    #pragma unroll
    for (int o = 1; o < 256; o <<= 1) {
        int t = (threadIdx.x >= o) ? sm[threadIdx.x - o] : 0;
        __syncthreads();
        sm[threadIdx.x] += t;
        __syncthreads();
    }
    g_bsums[threadIdx.x] = sm[threadIdx.x] - v;
}
__global__ void k_scan_finish() {
    int i = blockIdx.x * blockDim.x + threadIdx.x;
    if (i < NN) {
        int r = g_rowptr[i] + g_bsums[i >> 8];
        g_rowptr[i] = r;
        g_cursor[i] = r;
    }
    if (i == 0) g_rowptr[NN] = ET;
}
__global__ void k_scatter(const int* __restrict__ ei) {
    int e = blockIdx.x * blockDim.x + threadIdx.x;
    if (e >= ET) return;
    int src, dst;
    if (e < EE) { src = ei[e]; dst = ei[EE + e]; }
    else        { src = dst = e - EE; }
    int p = atomicAdd(&g_cursor[dst], 1);
    g_csr[p] = src;
}

// ---------------- W prep: fp32 [128k,128n] -> 2 half-K swizzled planes ------
__global__ void k_wprep(const float* __restrict__ W) {
    int i = blockIdx.x * blockDim.x + threadIdx.x;   // 2048 chunks
    if (i >= 2048) return;
    int n = i >> 4, kc = i & 15;
    uint32_t hp[4], lp[4];
    #pragma unroll
    for (int j = 0; j < 4; j++) {
        float w0 = W[(kc * 8 + 2 * j) * 128 + n];
        float w1 = W[(kc * 8 + 2 * j + 1) * 128 + n];
        __nv_bfloat16 h0 = __float2bfloat16_rn(w0);
        __nv_bfloat16 h1 = __float2bfloat16_rn(w1);
        __nv_bfloat162 hh; hh.x = h0; hh.y = h1;
        hp[j] = *(uint32_t*)&hh;
        lp[j] = pkbf(w0 - __bfloat162float(h0), w1 - __bfloat162float(h1));
    }
    int half = kc >> 3;
    uint32_t off = half * 16384 + soff64(n, kc & 7);
    *(uint4*)(g_wh + off) = make_uint4(hp[0], hp[1], hp[2], hp[3]);
    *(uint4*)(g_wl + off) = make_uint4(lp[0], lp[1], lp[2], lp[3]);
}

// ---------------- tensor-core GEMM + fused per-node alpha -------------------
// 128x128 tile, 512 threads (4x4 warps, warp tile 32x32), K in two 64-halves,
// 4 x 16KB smem planes -> 2 CTAs/SM.
// TERMS=3: D = Ah*Wh + Al*Wh + Ah*Wl (fp32 A split).
// TERMS=2: D = A*Wh + A*Wl (A pre-rounded to bf16; used for fp16 input).
template <int TERMS>
__global__ void __launch_bounds__(512, 2)
k_gemm_mma(const float* __restrict__ Af, const __half* __restrict__ Ahalf,
           const float* __restrict__ asrc, const float* __restrict__ adst,
           __half* __restrict__ H2, int M) {
    extern __shared__ __align__(16) char smem[];
    const int S_AH = 0, S_AL = 16384, S_BH = 32768, S_BL = 49152, S_ATT = 65536;
    int t = threadIdx.x;
    int row0 = blockIdx.x * 128;
    uint32_t sb = smem_u32(smem);
    float* att_s = (float*)(smem + S_ATT);      // [0..127] asrc, [128..255] adst

    if (t < 128)              att_s[t] = asrc[t];
    else if (t < 256)         att_s[t] = adst[t - 128];

    int wid = t >> 5, lane = t & 31;
    int wm = wid & 3;          // 4 row groups x 32 rows
    int wn = wid >> 2;         // 4 col groups x 32 cols (= head wn)

    float acc[2][4][4];
    #pragma unroll
    for (int mt = 0; mt < 2; mt++)
        #pragma unroll
        for (int nt = 0; nt < 4; nt++)
            #pragma unroll
            for (int q = 0; q < 4; q++) acc[mt][nt][q] = 0.f;

    int aRow = wm * 32 + (lane & 15);
    int aSel = lane >> 4;
    int bRow = wn * 32 + (lane & 7) + ((lane >> 4) << 3);
    int bSel = (lane >> 3) & 1;

    #pragma unroll
    for (int ks = 0; ks < 2; ks++) {
        if (ks) __syncthreads();     // previous mainloop must finish reading
        // copy pre-swizzled W half planes (2 x 16KB = 2 x 1024 uint4)
        {
            const uint4* wh4 = (const uint4*)g_wh + ks * 1024;
            const uint4* wl4 = (const uint4*)g_wl + ks * 1024;
            uint4* bh = (uint4*)(smem + S_BH);
            uint4* bl = (uint4*)(smem + S_BL);
            #pragma unroll
            for (int i = 0; i < 2; i++) {
                bh[i * 512 + t] = wh4[i * 512 + t];
                bl[i * 512 + t] = wl4[i * 512 + t];
            }
        }
        // convert A rows (128 rows x 8 chunks = 1024 chunks)
        #pragma unroll
        for (int ii = 0; ii < 2; ii++) {
            int i = ii * 512 + t;
            int r = i >> 3, kc = i & 7;
            int gr = row0 + r;
            int col = ks * 64 + kc * 8;
            float4 v0 = make_float4(0.f, 0.f, 0.f, 0.f), v1 = v0;
            if (gr < M) {
                if (TERMS == 2) {
                    uint4 raw = *(const uint4*)&Ahalf[gr * 128 + col];
                    float2 f0 = __half22float2(*(__half2*)&raw.x);
                    float2 f1p = __half22float2(*(__half2*)&raw.y);
                    float2 f2 = __half22float2(*(__half2*)&raw.z);
                    float2 f3 = __half22float2(*(__half2*)&raw.w);
                    v0 = make_float4(f0.x, f0.y, f1p.x, f1p.y);
                    v1 = make_float4(f2.x, f2.y, f3.x, f3.y);
                } else {
                    v0 = *(const float4*)&Af[gr * 128 + col];
                    v1 = *(const float4*)&Af[gr * 128 + col + 4];
                }
            }
            __nv_bfloat162 h0, h1, h2, h3;
            h0.x = __float2bfloat16_rn(v0.x); h0.y = __float2bfloat16_rn(v0.y);
            h1.x = __float2bfloat16_rn(v0.z); h1.y = __float2bfloat16_rn(v0.w);
            h2.x = __float2bfloat16_rn(v1.x); h2.y = __float2bfloat16_rn(v1.y);
            h3.x = __float2bfloat16_rn(v1.z); h3.y = __float2bfloat16_rn(v1.w);
            uint32_t off = soff64(r, kc);
            *(uint4*)(smem + S_AH + off) = make_uint4(*(uint32_t*)&h0, *(uint32_t*)&h1,
                                                      *(uint32_t*)&h2, *(uint32_t*)&h3);
            if (TERMS == 3) {
                *(uint4*)(smem + S_AL + off) = make_uint4(
                    pkbf(v0.x - __bfloat162float(h0.x), v0.y - __bfloat162float(h0.y)),
                    pkbf(v0.z - __bfloat162float(h1.x), v0.w - __bfloat162float(h1.y)),
                    pkbf(v1.x - __bfloat162float(h2.x), v1.y - __bfloat162float(h2.y)),
                    pkbf(v1.z - __bfloat162float(h3.x), v1.w - __bfloat162float(h3.y)));
            }
        }
        __syncthreads();

        // mainloop over this K half (4 x k16)
        #pragma unroll
        for (int k16 = 0; k16 < 4; k16++) {
            int kc = k16 * 2;
            uint32_t ah[2][4], al[2][4];
            #pragma unroll
            for (int mt = 0; mt < 2; mt++) {
                ldsm_x4(ah[mt][0], ah[mt][1], ah[mt][2], ah[mt][3],
                        sb + S_AH + soff64(aRow + mt * 16, kc + aSel));
                if (TERMS == 3)
                    ldsm_x4(al[mt][0], al[mt][1], al[mt][2], al[mt][3],
                            sb + S_AL + soff64(aRow + mt * 16, kc + aSel));
            }
            #pragma unroll
            for (int np = 0; np < 2; np++) {
                uint32_t bh0, bh1, bh2, bh3, bl0, bl1, bl2, bl3;
                ldsm_x4(bh0, bh1, bh2, bh3, sb + S_BH + soff64(bRow + np * 16, kc + bSel));
                ldsm_x4(bl0, bl1, bl2, bl3, sb + S_BL + soff64(bRow + np * 16, kc + bSel));
                #pragma unroll
                for (int mt = 0; mt < 2; mt++) {
                    mma16816(acc[mt][np * 2],     ah[mt][0], ah[mt][1], ah[mt][2], ah[mt][3], bh0, bh1);
                    mma16816(acc[mt][np * 2 + 1], ah[mt][0], ah[mt][1], ah[mt][2], ah[mt][3], bh2, bh3);
                    if (TERMS == 3) {
                        mma16816(acc[mt][np * 2],     al[mt][0], al[mt][1], al[mt][2], al[mt][3], bh0, bh1);
                        mma16816(acc[mt][np * 2 + 1], al[mt][0], al[mt][1], al[mt][2], al[mt][3], bh2, bh3);
                    }
                    mma16816(acc[mt][np * 2],     ah[mt][0], ah[mt][1], ah[mt][2], ah[mt][3], bl0, bl1);
                    mma16816(acc[mt][np * 2 + 1], ah[mt][0], ah[mt][1], ah[mt][2], ah[mt][3], bl2, bl3);
                }
            }
        }
    }

    // epilogue: fp16 feature store + fused alpha (head h = wn)
    #pragma unroll
    for (int mt = 0; mt < 2; mt++) {
        int rg = row0 + wm * 32 + mt * 16 + (lane >> 2);
        #pragma unroll
        for (int nt = 0; nt < 4; nt++) {
            int n = wn * 32 + nt * 8 + (lane & 3) * 2;
            if (rg < M) {
                __half2 hv; hv.x = __float2half(acc[mt][nt][0]); hv.y = __float2half(acc[mt][nt][1]);
                *(__half2*)&H2[rg * 128 + n] = hv;
            }
            if (rg + 8 < M) {
                __half2 hv; hv.x = __float2half(acc[mt][nt][2]); hv.y = __float2half(acc[mt][nt][3]);
                *(__half2*)&H2[(rg + 8) * 128 + n] = hv;
            }
        }
        float ps0 = 0.f, pd0 = 0.f, ps1 = 0.f, pd1 = 0.f;
        #pragma unroll
        for (int nt = 0; nt < 4; nt++) {
            int n = wn * 32 + nt * 8 + (lane & 3) * 2;
            float w0s = att_s[n], w1s = att_s[n + 1];
            float w0d = att_s[128 + n], w1d = att_s[128 + n + 1];
            ps0 += acc[mt][nt][0] * w0s + acc[mt][nt][1] * w1s;
            pd0 += acc[mt][nt][0] * w0d + acc[mt][nt][1] * w1d;
            ps1 += acc[mt][nt][2] * w0s + acc[mt][nt][3] * w1s;
            pd1 += acc[mt][nt][2] * w0d + acc[mt][nt][3] * w1d;
        }
        #pragma unroll
        for (int o = 1; o <= 2; o <<= 1) {
            ps0 += __shfl_xor_sync(0xffffffffu, ps0, o);
            pd0 += __shfl_xor_sync(0xffffffffu, pd0, o);
            ps1 += __shfl_xor_sync(0xffffffffu, ps1, o);
            pd1 += __shfl_xor_sync(0xffffffffu, pd1, o);
        }
        if ((lane & 3) == 0) {
            if (rg < M) {
                g_alpha[rg * 8 + wn]     = ps0;
                g_alpha[rg * 8 + 4 + wn] = pd0;
            }
            if (rg + 8 < M) {
                g_alpha[(rg + 8) * 8 + wn]     = ps1;
                g_alpha[(rg + 8) * 8 + 4 + wn] = pd1;
            }
        }
    }
}

// ---------------- edge softmax + aggregation (H=4, C=32) --------------------
// Single edge pass; features gathered in fp16 (2 x 128B lines per edge).
// mode 0: write ELU(out) fp16 to `outh` (feeds next GEMM).
// mode 1: fuse layer-3 prep — dot ELU(out) with W3 -> g_hw3, alphas -> g_a3.
__global__ void k_aggregate4(const __half* __restrict__ h2,
                             const float* __restrict__ bias,
                             __half* __restrict__ outh, int mode,
                             const float* __restrict__ W3,
                             const float* __restrict__ as3,
                             const float* __restrict__ ad3) {
    __shared__ float4 sm_e[8][32];
    __shared__ int    sm_s[8][32];
    int n = (blockIdx.x * blockDim.x + threadIdx.x) >> 5;
    if (n >= NN) return;
    int lane = threadIdx.x & 31;
    int wrp  = (threadIdx.x >> 5);
    int hsel = lane >> 4;
    int s0 = g_rowptr[n], s1 = g_rowptr[n + 1];
    float4 ad = *(const float4*)&g_alpha[n * 8 + 4];

    float sum0 = 0.f, sum1 = 0.f, sum2 = 0.f, sum3 = 0.f;
    float2 accA = make_float2(0.f, 0.f), accB = make_float2(0.f, 0.f);
    for (int base = s0; base < s1; base += 32) {
        int i = base + lane;
        int s = 0;
        float4 e = make_float4(0.f, 0.f, 0.f, 0.f);
        if (i < s1) {
            s = g_csr[i];
            float4 al = *(const float4*)&g_alpha[s * 8];
            float a;
            a = al.x + ad.x; a = (a > 0.f) ? a : NEG_SLOPE * a; e.x = __expf(a); sum0 += e.x;
            a = al.y + ad.y; a = (a > 0.f) ? a : NEG_SLOPE * a; e.y = __expf(a); sum1 += e.y;
            a = al.z + ad.z; a = (a > 0.f) ? a : NEG_SLOPE * a; e.z = __expf(a); sum2 += e.z;
            a = al.w + ad.w; a = (a > 0.f) ? a : NEG_SLOPE * a; e.w = __expf(a); sum3 += e.w;
        }
        sm_s[wrp][lane] = s;
        sm_e[wrp][lane] = e;
        __syncwarp();
        int cnt = min(32, s1 - base);
        #pragma unroll 8
        for (int j = 0; j < cnt; j++) {
            int ss = sm_s[wrp][j];
            float4 ee = sm_e[wrp][j];
            const __half2* hp = (const __half2*)(h2 + ss * FDIM);
            float2 fa = __half22float2(hp[lane]);
            float2 fb = __half22float2(hp[32 + lane]);
            float wA = hsel ? ee.y : ee.x;
            float wB = hsel ? ee.w : ee.z;
            accA.x += wA * fa.x; accA.y += wA * fa.y;
            accB.x += wB * fb.x; accB.y += wB * fb.y;
        }
        __syncwarp();
    }
    float inv0 = 1.f / wsum(sum0);
    float inv1 = 1.f / wsum(sum1);
    float inv2 = 1.f / wsum(sum2);
    float inv3 = 1.f / wsum(sum3);
    float invA = hsel ? inv1 : inv0;
    float invB = hsel ? inv3 : inv2;

    int c = 2 * lane;
    float v0 = accA.x * invA + bias[c];
    float v1 = accA.y * invA + bias[c + 1];
    float v2 = accB.x * invB + bias[64 + c];
    float v3 = accB.y * invB + bias[64 + c + 1];
    v0 = (v0 > 0.f) ? v0 : (__expf(v0) - 1.f);
    v1 = (v1 > 0.f) ? v1 : (__expf(v1) - 1.f);
    v2 = (v2 > 0.f) ? v2 : (__expf(v2) - 1.f);
    v3 = (v3 > 0.f) ? v3 : (__expf(v3) - 1.f);

    if (mode == 0) {
        __half2 o0; o0.x = __float2half(v0); o0.y = __float2half(v1);
        __half2 o1; o1.x = __float2half(v2); o1.y = __float2half(v3);
        *(__half2*)&outh[n * FDIM + c]      = o0;
        *(__half2*)&outh[n * FDIM + 64 + c] = o1;
    } else {
        // layer-3 prep: hw3 = f2 @ W3 ([128,2]); a3 from as3/ad3
        float4 wA4 = *(const float4*)&W3[2 * c];
        float4 wB4 = *(const float4*)&W3[128 + 2 * c];
        float p0 = v0 * wA4.x + v1 * wA4.z + v2 * wB4.x + v3 * wB4.z;
        float p1 = v0 * wA4.y + v1 * wA4.w + v2 * wB4.y + v3 * wB4.w;
        p0 = wsum(p0); p1 = wsum(p1);
        if (lane == 0) {
            g_hw3[n * 2] = p0; g_hw3[n * 2 + 1] = p1;
            g_a3[n * 2]     = p0 * as3[0] + p1 * as3[1];
            g_a3[n * 2 + 1] = p0 * ad3[0] + p1 * ad3[1];
        }
    }
}

// layer-3 aggregate (H=1,C=2) + bias + log_softmax, single edge pass
__global__ void k_aggregate1(const float* __restrict__ b3, float* __restrict__ out) {
    int n = (blockIdx.x * blockDim.x + threadIdx.x) >> 5;
    if (n >= NN) return;
    int lane = threadIdx.x & 31;
    int s0 = g_rowptr[n], s1 = g_rowptr[n + 1];
    float ad = g_a3[n * 2 + 1];

    float sum = 0.f, a0 = 0.f, a1 = 0.f;
    for (int i = s0 + lane; i < s1; i += 32) {
        int s = g_csr[i];
        float2 al = *(const float2*)&g_a3[s * 2];
        float a = al.x + ad;
        a = (a > 0.f) ? a : NEG_SLOPE * a;
        float e = __expf(a);
        sum += e;
        float2 h = *(const float2*)&g_hw3[s * 2];
        a0 += e * h.x;
        a1 += e * h.y;
    }
    sum = wsum(sum); a0 = wsum(a0); a1 = wsum(a1);

    if (lane == 0) {
        float inv = 1.f / sum;
        float z0 = a0 * inv + b3[0];
        float z1 = a1 * inv + b3[1];
        float mx = fmaxf(z0, z1);
        float l  = logf(__expf(z0 - mx) + __expf(z1 - mx));
        out[n * 2]     = z0 - mx - l;
        out[n * 2 + 1] = z1 - mx - l;
    }
}

// ---------------- host driver -----------------------------------------------
extern "C" void kernel_launch(void* const* d_in, const int* in_sizes, int n_in,
                              void* d_out, int out_size) {
    const float* x   = (const float*)d_in[0];
    const int*   ei  = (const int*)  d_in[1];
    const float* W1  = (const float*)d_in[2];
    const float* as1 = (const float*)d_in[3];
    const float* ad1 = (const float*)d_in[4];
    const float* b1  = (const float*)d_in[5];
    const float* W2  = (const float*)d_in[6];
    const float* as2 = (const float*)d_in[7];
    const float* ad2 = (const float*)d_in[8];
    const float* b2  = (const float*)d_in[9];
    const float* W3  = (const float*)d_in[10];
    const float* as3 = (const float*)d_in[11];
    const float* ad3 = (const float*)d_in[12];
    const float* b3  = (const float*)d_in[13];
    float* out = (float*)d_out;

    __half *p_h2, *p_f1h;
    cudaGetSymbolAddress((void**)&p_h2, g_h2);
    cudaGetSymbolAddress((void**)&p_f1h, g_f1h);

    const int GEMM_SMEM = 65536 + 1024;    // 4 x 16KB planes + att
    cudaFuncSetAttribute(k_gemm_mma<3>, cudaFuncAttributeMaxDynamicSharedMemorySize, GEMM_SMEM);
    cudaFuncSetAttribute(k_gemm_mma<2>, cudaFuncAttributeMaxDynamicSharedMemorySize, GEMM_SMEM);

    // one-time host resources
    static cudaStream_t s1 = nullptr;
    static cudaEvent_t evFork = nullptr, evCsr = nullptr, evG1 = nullptr, evW2 = nullptr;
    if (!s1) {
        cudaStreamCreateWithFlags(&s1, cudaStreamNonBlocking);
        cudaEventCreateWithFlags(&evFork, cudaEventDisableTiming);
        cudaEventCreateWithFlags(&evCsr,  cudaEventDisableTiming);
        cudaEventCreateWithFlags(&evG1,   cudaEventDisableTiming);
        cudaEventCreateWithFlags(&evW2,   cudaEventDisableTiming);
    }

    const int TPB = 256;
    int nbN = (NN + TPB - 1) / TPB;           // 196
    int nbE = (ET + TPB - 1) / TPB;           // 3321
    int nbW = (NN * 32 + TPB - 1) / TPB;      // 6250 (warp per node)
    int nbT = (NN + 127) / 128;               // 391 gemm tiles

    // fork: CSR branch on s1, GEMM branch on the launch stream (0)
    cudaEventRecord(evFork, 0);
    cudaStreamWaitEvent(s1, evFork, 0);

    // --- branch A (s1): CSR build ---
    k_zero_cnt<<<nbN, TPB, 0, s1>>>();
    k_hist<<<nbE, TPB, 0, s1>>>(ei);
    k_scan_block<<<nbN, TPB, 0, s1>>>();
    k_scan_tops<<<1, 256, 0, s1>>>(nbN);
    k_scan_finish<<<nbN, TPB, 0, s1>>>();
    k_scatter<<<nbE, TPB, 0, s1>>>(ei);
    cudaEventRecord(evCsr, s1);

    // --- branch B (stream 0): W1 prep + GEMM1 ---
    k_wprep<<<16, 128>>>(W1);
    k_gemm_mma<3><<<nbT, 512, GEMM_SMEM>>>(x, nullptr, as1, ad1, p_h2, NN);
    cudaEventRecord(evG1, 0);

    // W2 prep on s1, overlapped with layer-1 aggregation
    cudaStreamWaitEvent(s1, evG1, 0);
    k_wprep<<<16, 128, 0, s1>>>(W2);
    cudaEventRecord(evW2, s1);

    // join: layer-1 aggregation needs CSR + GEMM1
    cudaStreamWaitEvent(0, evCsr, 0);
    k_aggregate4<<<nbW, TPB>>>(p_h2, b1, p_f1h, 0, W3, as3, ad3);

    // layer 2 (needs W2 planes)
    cudaStreamWaitEvent(0, evW2, 0);
    k_gemm_mma<2><<<nbT, 512, GEMM_SMEM>>>(nullptr, p_f1h, as2, ad2, p_h2, NN);
    k_aggregate4<<<nbW, TPB>>>(p_h2, b2, nullptr, 1, W3, as3, ad3);

    // layer 3 final aggregate + log_softmax
    k_aggregate1<<<nbW, TPB>>>(b3, out);
}